// round 6
// baseline (speedup 1.0000x reference)
#include <cuda_runtime.h>

#define NN 100000
#define NE 1250000
#define D  64
#define EF 13
#define SCAN_B 1024

// ---------------- scratch (device globals; no allocation allowed) ----------------
__device__ float g_sm[EF];
__device__ int   g_is64;
__device__ int   g_rows[NE];
__device__ int   g_cols[NE];
__device__ float g_ew[NE];
__device__ float g_deg[NN];
__device__ float g_dinv[NN];
__device__ float g_dsq[NN];
__device__ int   g_cnt[NN];       // in-degree (edge count per dest)
__device__ int   g_start[NN];     // CSR offsets
__device__ int   g_cursor[NN];    // build cursors
__device__ int   g_bsum[128];     // scan partials
__device__ int   g_boff[128];
__device__ __align__(16) uint2 g_edge[NE];      // packed (row, norm) sorted by col
__device__ __align__(16) float g_bufA[NN * D];  // x1
__device__ __align__(16) float g_bufB[NN * D];  // x2
__device__ float g_S[3 * D];      // pool numerators
__device__ float g_Z[3];          // pool denominators

// ---------------- init: softmax(aaaaa), zero pool accs, detect index dtype -------
__global__ void k_init(const float* __restrict__ aaaaa,
                       const int* __restrict__ ei_raw) {
    int t = threadIdx.x;
    if (t < 3 * D) g_S[t] = 0.0f;
    if (t < 3)     g_Z[t] = 0.0f;
    if (t == 0) {
        float v[EF];
        float m = -1e30f;
        for (int j = 0; j < EF; j++) { v[j] = aaaaa[j]; m = fmaxf(m, v[j]); }
        float s = 0.0f;
        for (int j = 0; j < EF; j++) { v[j] = expf(v[j] - m); s += v[j]; }
        for (int j = 0; j < EF; j++) g_sm[j] = v[j] / s;

        // dtype sniff: int64 indices have zero high words
        int is64 = 1;
        for (int i = 0; i < 64; i++)
            if (ei_raw[2 * i + 1] != 0) { is64 = 0; break; }
        g_is64 = is64;
    }
}

// ---------------- decode edge_index into int32 rows/cols --------------------------
__global__ void k_decode(const void* __restrict__ ei, int E) {
    int e = blockIdx.x * blockDim.x + threadIdx.x;
    if (e >= E) return;
    if (g_is64) {
        const long long* p = (const long long*)ei;
        g_rows[e] = (int)p[e];
        g_cols[e] = (int)p[E + e];
    } else {
        const int* p = (const int*)ei;
        g_rows[e] = p[e];
        g_cols[e] = p[E + e];
    }
}

// ---------------- per-node init: deg=1 (self loop), cnt=0 ------------------------
__global__ void k_deginit(int n) {
    int i = blockIdx.x * blockDim.x + threadIdx.x;
    if (i < n) { g_deg[i] = 1.0f; g_cnt[i] = 0; }
}

// ---------- edge weight + float deg + int count (direct loads; L1-coalesced) -----
__global__ void k_ewdeg(const float* __restrict__ ea, int E) {
    int e = blockIdx.x * blockDim.x + threadIdx.x;
    if (e >= E) return;
    const float* row = ea + (long long)e * EF;
    float s = 0.0f;
#pragma unroll
    for (int j = 0; j < EF; j++) s += __ldg(row + j) * g_sm[j];
    g_ew[e] = s;
    int c = g_cols[e];
    atomicAdd(&g_deg[c], s);
    atomicAdd(&g_cnt[c], 1);
}

// ---------------- deg^{-1/2} and self-loop norm -----------------------------------
__global__ void k_dinv(int n) {
    int i = blockIdx.x * blockDim.x + threadIdx.x;
    if (i >= n) return;
    float di = rsqrtf(g_deg[i]);   // deg >= 1 always
    g_dinv[i] = di;
    g_dsq[i] = di * di;
}

// ---------------- scan stage A: per-block sums of g_cnt ---------------------------
__global__ void k_scanA(int n) {
    __shared__ int sm[SCAN_B];
    int i = blockIdx.x * SCAN_B + threadIdx.x;
    sm[threadIdx.x] = (i < n) ? g_cnt[i] : 0;
    __syncthreads();
    for (int off = SCAN_B / 2; off > 0; off >>= 1) {
        if (threadIdx.x < off) sm[threadIdx.x] += sm[threadIdx.x + off];
        __syncthreads();
    }
    if (threadIdx.x == 0) g_bsum[blockIdx.x] = sm[0];
}

// ---------------- scan stage B: exclusive scan of block sums ----------------------
__global__ void k_scanB(int nblk) {
    if (threadIdx.x == 0) {
        int run = 0;
        for (int i = 0; i < nblk; i++) { g_boff[i] = run; run += g_bsum[i]; }
    }
}

// ---------------- scan stage C: in-block exclusive scan + base; init cursor -------
__global__ void k_scanC(int n) {
    __shared__ int sm[SCAN_B];
    int i = blockIdx.x * SCAN_B + threadIdx.x;
    int v = (i < n) ? g_cnt[i] : 0;
    sm[threadIdx.x] = v;
    __syncthreads();
    for (int off = 1; off < SCAN_B; off <<= 1) {
        int t = (threadIdx.x >= off) ? sm[threadIdx.x - off] : 0;
        __syncthreads();
        sm[threadIdx.x] += t;
        __syncthreads();
    }
    if (i < n) {
        int st = g_boff[blockIdx.x] + sm[threadIdx.x] - v;  // exclusive
        g_start[i] = st;
        g_cursor[i] = st;
    }
}

// ---------------- CSR build: pack (row, norm) sorted by destination ---------------
__global__ void k_build(int E) {
    int e = blockIdx.x * blockDim.x + threadIdx.x;
    if (e >= E) return;
    int r = g_rows[e];
    int c = g_cols[e];
    float nrm = g_dinv[r] * g_ew[e] * g_dinv[c];
    int pos = atomicAdd(&g_cursor[c], 1);
    g_edge[pos] = make_uint2((unsigned)r, __float_as_uint(nrm));
}

// ===== fused layer: CSR aggregate(x) -> in-warp GEMM (agg@W) -> bias/relu =========
// ===== -> store next x (optional) -> attention pool ================================
// Uses Agg(x@W) == (Agg x)@W. Warp per node, grid-stride.
__global__ void __launch_bounds__(256) k_layer(
        const float* __restrict__ xext, int sel_in, int sel_out,
        const float* __restrict__ W, const float* __restrict__ b,
        const float* __restrict__ wg, const float* __restrict__ bg,
        int layer, int n) {
    __shared__ float Ws[D * D];
    __shared__ float ps0[8][32];
    __shared__ float ps1[8][32];
    __shared__ float pz[8];

    for (int i = threadIdx.x; i < D * D; i += blockDim.x) Ws[i] = W[i];
    __syncthreads();

    const float* xi = (sel_in == 0) ? xext : ((sel_in == 1) ? g_bufA : g_bufB);
    float* xo = (sel_out == 1) ? g_bufA : ((sel_out == 2) ? g_bufB : 0);

    int lane = threadIdx.x & 31;
    int wlocal = threadIdx.x >> 5;
    int warp = (blockIdx.x * blockDim.x + threadIdx.x) >> 5;
    int nwarps = (gridDim.x * blockDim.x) >> 5;

    float wg0 = wg[lane], wg1 = wg[lane + 32];
    float b0 = b[lane],  b1 = b[lane + 32];
    float bgv = bg[0];

    float s0 = 0.f, s1 = 0.f, z = 0.f;

    for (int i = warp; i < n; i += nwarps) {
        // ---- aggregate raw features: a = dsq[i]*x[i] + sum norm*x[row] ----
        const float* xrow = xi + (long long)i * D;
        float ds = g_dsq[i];
        float a0 = ds * xrow[lane];
        float a1 = ds * xrow[lane + 32];

        int j = g_start[i];
        int end = j + g_cnt[i];
        // 4-edge unroll: all records + payload loads issued before FMAs (MLP~8)
        for (; j + 3 < end; j += 4) {
            uint2 p0 = g_edge[j];
            uint2 p1 = g_edge[j + 1];
            uint2 p2 = g_edge[j + 2];
            uint2 p3 = g_edge[j + 3];
            const float* r0 = xi + (long long)p0.x * D;
            const float* r1 = xi + (long long)p1.x * D;
            const float* r2 = xi + (long long)p2.x * D;
            const float* r3 = xi + (long long)p3.x * D;
            float f00 = r0[lane], f01 = r0[lane + 32];
            float f10 = r1[lane], f11 = r1[lane + 32];
            float f20 = r2[lane], f21 = r2[lane + 32];
            float f30 = r3[lane], f31 = r3[lane + 32];
            float n0 = __uint_as_float(p0.y);
            float n1 = __uint_as_float(p1.y);
            float n2 = __uint_as_float(p2.y);
            float n3 = __uint_as_float(p3.y);
            a0 = fmaf(n0, f00, a0); a1 = fmaf(n0, f01, a1);
            a0 = fmaf(n1, f10, a0); a1 = fmaf(n1, f11, a1);
            a0 = fmaf(n2, f20, a0); a1 = fmaf(n2, f21, a1);
            a0 = fmaf(n3, f30, a0); a1 = fmaf(n3, f31, a1);
        }
        for (; j < end; j++) {
            uint2 p0 = g_edge[j];
            const float* r0 = xi + (long long)p0.x * D;
            float nn = __uint_as_float(p0.y);
            a0 = fmaf(nn, r0[lane], a0);
            a1 = fmaf(nn, r0[lane + 32], a1);
        }

        // ---- in-warp GEMM: v[c] = sum_k a[k] * W[k][c] ----
        float o0 = 0.f, o1 = 0.f;
#pragma unroll
        for (int k = 0; k < 32; k++) {
            float ak  = __shfl_sync(0xffffffffu, a0, k);   // a[k]
            float ak2 = __shfl_sync(0xffffffffu, a1, k);   // a[k+32]
            o0 = fmaf(ak,  Ws[k * D + lane],        o0);
            o1 = fmaf(ak,  Ws[k * D + lane + 32],   o1);
            o0 = fmaf(ak2, Ws[(k + 32) * D + lane],      o0);
            o1 = fmaf(ak2, Ws[(k + 32) * D + lane + 32], o1);
        }

        float v0 = fmaxf(o0 + b0, 0.f);
        float v1 = fmaxf(o1 + b1, 0.f);
        if (xo) {
            long long idx = (long long)i * D + lane;
            xo[idx] = v0;
            xo[idx + 32] = v1;
        }

        // ---- attention pool partials ----
        float dot = v0 * wg0 + v1 * wg1;
#pragma unroll
        for (int off = 16; off > 0; off >>= 1)
            dot += __shfl_xor_sync(0xffffffffu, dot, off);
        float sg = 1.0f / (1.0f + expf(-(dot + bgv)));  // sigmoid gate
        float w = expf(sg);                             // softmax numerator
        s0 += w * v0;
        s1 += w * v1;
        if (lane == 0) z += w;
    }

    // block-level reduction of pool partials, one atomic set per block
    ps0[wlocal][lane] = s0;
    ps1[wlocal][lane] = s1;
    if (lane == 0) pz[wlocal] = z;
    __syncthreads();
    if (wlocal == 0) {
        float t0 = 0.f, t1 = 0.f, tz = 0.f;
#pragma unroll
        for (int w8 = 0; w8 < 8; w8++) {
            t0 += ps0[w8][lane];
            t1 += ps1[w8][lane];
            if (lane == 0) tz += pz[w8];
        }
        atomicAdd(&g_S[layer * D + lane], t0);
        atomicAdd(&g_S[layer * D + lane + 32], t1);
        if (lane == 0) atomicAdd(&g_Z[layer], tz);
    }
}

// ---------------- final divide ----------------------------------------------------
__global__ void k_out(float* __restrict__ out) {
    int t = threadIdx.x;
    if (t < 3 * D) out[t] = g_S[t] / g_Z[t / D];
}

// ---------------- launch ----------------------------------------------------------
extern "C" void kernel_launch(void* const* d_in, const int* in_sizes, int n_in,
                              void* d_out, int out_size) {
    const float* x     = (const float*)d_in[0];
    const void*  ei    = d_in[1];
    const float* ea    = (const float*)d_in[2];
    const float* aaaaa = (const float*)d_in[3];
    const float* W[3]  = {(const float*)d_in[4], (const float*)d_in[6], (const float*)d_in[8]};
    const float* b[3]  = {(const float*)d_in[5], (const float*)d_in[7], (const float*)d_in[9]};
    const float* wg[3] = {(const float*)d_in[10], (const float*)d_in[12], (const float*)d_in[14]};
    const float* bg[3] = {(const float*)d_in[11], (const float*)d_in[13], (const float*)d_in[15]};
    float* out = (float*)d_out;

    int N = in_sizes[0] / D;     // 100000
    int E = in_sizes[2] / EF;    // 1250000
    int nblk = (N + SCAN_B - 1) / SCAN_B;

    k_init<<<1, 256>>>(aaaaa, (const int*)ei);
    k_decode<<<(E + 255) / 256, 256>>>(ei, E);
    k_deginit<<<(N + 255) / 256, 256>>>(N);
    k_ewdeg<<<(E + 255) / 256, 256>>>(ea, E);
    k_dinv<<<(N + 255) / 256, 256>>>(N);
    k_scanA<<<nblk, SCAN_B>>>(N);
    k_scanB<<<1, 32>>>(nblk);
    k_scanC<<<nblk, SCAN_B>>>(N);
    k_build<<<(E + 255) / 256, 256>>>(E);

    // layer 1: x(ext) -> bufA, pool 0
    k_layer<<<1024, 256>>>(x, 0, 1, W[0], b[0], wg[0], bg[0], 0, N);
    // layer 2: bufA -> bufB, pool 1
    k_layer<<<1024, 256>>>(x, 1, 2, W[1], b[1], wg[1], bg[1], 1, N);
    // layer 3: bufB -> (pool only), pool 2
    k_layer<<<1024, 256>>>(x, 2, 0, W[2], b[2], wg[2], bg[2], 2, N);

    k_out<<<1, 192>>>(out);
}

// round 7
// speedup vs baseline: 1.1451x; 1.1451x over previous
#include <cuda_runtime.h>
#include <cuda_fp16.h>

#define NN 100000
#define NE 1250000
#define D  64
#define EF 13
#define SCAN_B 1024

// ---------------- scratch (device globals; no allocation allowed) ----------------
__device__ float g_sm[EF];
__device__ int   g_is64;
__device__ int   g_rows[NE];
__device__ int   g_cols[NE];
__device__ float g_ew[NE];
__device__ float g_deg[NN];
__device__ float g_dinv[NN];
__device__ float g_dsq[NN];
__device__ int   g_cnt[NN];       // in-degree (edge count per dest)
__device__ int   g_start[NN];     // CSR offsets
__device__ int   g_cursor[NN];    // build cursors
__device__ int   g_bsum[128];     // scan partials
__device__ int   g_boff[128];
__device__ __align__(16) uint2 g_edge[NE];       // packed (row, norm) sorted by col
__device__ __align__(16) __half g_hh[NN * D];    // GEMM output, fp16 (gather payload)
__device__ __align__(16) float g_bufA[NN * D];   // x1
__device__ __align__(16) float g_bufB[NN * D];   // x2
__device__ float g_S[3 * D];      // pool numerators
__device__ float g_Z[3];          // pool denominators

// ---------------- init: softmax(aaaaa), zero pool accs, detect index dtype -------
__global__ void k_init(const float* __restrict__ aaaaa,
                       const int* __restrict__ ei_raw) {
    int t = threadIdx.x;
    if (t < 3 * D) g_S[t] = 0.0f;
    if (t < 3)     g_Z[t] = 0.0f;
    if (t == 0) {
        float v[EF];
        float m = -1e30f;
        for (int j = 0; j < EF; j++) { v[j] = aaaaa[j]; m = fmaxf(m, v[j]); }
        float s = 0.0f;
        for (int j = 0; j < EF; j++) { v[j] = expf(v[j] - m); s += v[j]; }
        for (int j = 0; j < EF; j++) g_sm[j] = v[j] / s;

        // dtype sniff: int64 indices have zero high words
        int is64 = 1;
        for (int i = 0; i < 64; i++)
            if (ei_raw[2 * i + 1] != 0) { is64 = 0; break; }
        g_is64 = is64;
    }
}

// ---------------- per-node init: deg=1 (self loop), cnt=0 ------------------------
__global__ void k_deginit(int n) {
    int i = blockIdx.x * blockDim.x + threadIdx.x;
    if (i < n) { g_deg[i] = 1.0f; g_cnt[i] = 0; }
}

// ------- decode edge_index into int32 rows/cols + per-dest edge count ------------
__global__ void k_decode(const void* __restrict__ ei, int E) {
    int e = blockIdx.x * blockDim.x + threadIdx.x;
    if (e >= E) return;
    int r, c;
    if (g_is64) {
        const long long* p = (const long long*)ei;
        r = (int)p[e];
        c = (int)p[E + e];
    } else {
        const int* p = (const int*)ei;
        r = p[e];
        c = p[E + e];
    }
    g_rows[e] = r;
    g_cols[e] = c;
    atomicAdd(&g_cnt[c], 1);
}

// ---------- edge weight + float deg (direct loads; L1-coalesced) ------------------
__global__ void k_ewdeg(const float* __restrict__ ea, int E) {
    int e = blockIdx.x * blockDim.x + threadIdx.x;
    if (e >= E) return;
    const float* row = ea + (long long)e * EF;
    float s = 0.0f;
#pragma unroll
    for (int j = 0; j < EF; j++) s += __ldg(row + j) * g_sm[j];
    g_ew[e] = s;
    atomicAdd(&g_deg[g_cols[e]], s);
}

// ---------------- deg^{-1/2} and self-loop norm -----------------------------------
__global__ void k_dinv(int n) {
    int i = blockIdx.x * blockDim.x + threadIdx.x;
    if (i >= n) return;
    float di = rsqrtf(g_deg[i]);   // deg >= 1 always
    g_dinv[i] = di;
    g_dsq[i] = di * di;
}

// ---------------- scan stage A: per-block sums of g_cnt ---------------------------
__global__ void k_scanA(int n) {
    __shared__ int sm[SCAN_B];
    int i = blockIdx.x * SCAN_B + threadIdx.x;
    sm[threadIdx.x] = (i < n) ? g_cnt[i] : 0;
    __syncthreads();
    for (int off = SCAN_B / 2; off > 0; off >>= 1) {
        if (threadIdx.x < off) sm[threadIdx.x] += sm[threadIdx.x + off];
        __syncthreads();
    }
    if (threadIdx.x == 0) g_bsum[blockIdx.x] = sm[0];
}

// ---------------- scan stage B: exclusive scan of block sums ----------------------
__global__ void k_scanB(int nblk) {
    if (threadIdx.x == 0) {
        int run = 0;
        for (int i = 0; i < nblk; i++) { g_boff[i] = run; run += g_bsum[i]; }
    }
}

// ---------------- scan stage C: in-block exclusive scan + base; init cursor -------
__global__ void k_scanC(int n) {
    __shared__ int sm[SCAN_B];
    int i = blockIdx.x * SCAN_B + threadIdx.x;
    int v = (i < n) ? g_cnt[i] : 0;
    sm[threadIdx.x] = v;
    __syncthreads();
    for (int off = 1; off < SCAN_B; off <<= 1) {
        int t = (threadIdx.x >= off) ? sm[threadIdx.x - off] : 0;
        __syncthreads();
        sm[threadIdx.x] += t;
        __syncthreads();
    }
    if (i < n) {
        int st = g_boff[blockIdx.x] + sm[threadIdx.x] - v;  // exclusive
        g_start[i] = st;
        g_cursor[i] = st;
    }
}

// ---------------- CSR build: pack (row, norm) sorted by destination ---------------
__global__ void k_build(int E) {
    int e = blockIdx.x * blockDim.x + threadIdx.x;
    if (e >= E) return;
    int r = g_rows[e];
    int c = g_cols[e];
    float nrm = g_dinv[r] * g_ew[e] * g_dinv[c];
    int pos = atomicAdd(&g_cursor[c], 1);
    g_edge[pos] = make_uint2((unsigned)r, __float_as_uint(nrm));
}

// ---------------- GEMM: h = x @ W  (thread per row, W in smem; fp16 output) -------
__global__ void k_gemm(const float* __restrict__ xext, int sel,
                       const float* __restrict__ W, int n) {
    __shared__ float Ws[D * D];
    for (int i = threadIdx.x; i < D * D; i += blockDim.x) Ws[i] = W[i];
    __syncthreads();

    const float* x = (sel == 0) ? xext : ((sel == 1) ? g_bufA : g_bufB);
    int row = blockIdx.x * blockDim.x + threadIdx.x;
    if (row >= n) return;

    const float4* xr = (const float4*)(x + (long long)row * D);
    float4 acc[16];
#pragma unroll
    for (int c = 0; c < 16; c++) acc[c] = make_float4(0.f, 0.f, 0.f, 0.f);

#pragma unroll
    for (int k4 = 0; k4 < 16; k4++) {
        float4 xv = xr[k4];
        float xa[4] = {xv.x, xv.y, xv.z, xv.w};
#pragma unroll
        for (int kk = 0; kk < 4; kk++) {
            float xk = xa[kk];
            const float4* wrow = (const float4*)&Ws[(k4 * 4 + kk) * D];
#pragma unroll
            for (int c = 0; c < 16; c++) {
                float4 wv = wrow[c];
                acc[c].x += xk * wv.x;
                acc[c].y += xk * wv.y;
                acc[c].z += xk * wv.z;
                acc[c].w += xk * wv.w;
            }
        }
    }
    __half2* ho = (__half2*)(g_hh + (long long)row * D);
#pragma unroll
    for (int c = 0; c < 16; c++) {
        ho[2 * c]     = __float22half2_rn(make_float2(acc[c].x, acc[c].y));
        ho[2 * c + 1] = __float22half2_rn(make_float2(acc[c].z, acc[c].w));
    }
}

// ------ fused CSR aggregate (+self loop, fp16 payload) + bias/relu + pool ---------
// warp per node (grid-stride); lane owns features (2l, 2l+1); 128B/edge gather.
__global__ void __launch_bounds__(256) k_aggpool(
        int sel_out, const float* __restrict__ b,
        const float* __restrict__ wg, const float* __restrict__ bg,
        int layer, int n) {
    __shared__ float ps0[8][32];
    __shared__ float ps1[8][32];
    __shared__ float pz[8];
    float* xo = (sel_out == 1) ? g_bufA : ((sel_out == 2) ? g_bufB : 0);
    int lane = threadIdx.x & 31;
    int wlocal = threadIdx.x >> 5;
    int warp = (blockIdx.x * blockDim.x + threadIdx.x) >> 5;
    int nwarps = (gridDim.x * blockDim.x) >> 5;

    float wg0 = wg[2 * lane], wg1 = wg[2 * lane + 1];
    float b0 = b[2 * lane],  b1 = b[2 * lane + 1];
    float bgv = bg[0];

    const __half2* hp = (const __half2*)g_hh;   // element index = row*32 + lane

    float s0 = 0.f, s1 = 0.f, z = 0.f;

    for (int i = warp; i < n; i += nwarps) {
        float ds = g_dsq[i];
        float2 hv = __half22float2(hp[(long long)i * 32 + lane]);
        float a0 = ds * hv.x;
        float a1 = ds * hv.y;

        int j = g_start[i];
        int end = j + g_cnt[i];
        // 4-edge unroll: 4 record loads + 4 half2 payload loads in flight
        for (; j + 3 < end; j += 4) {
            uint2 p0 = g_edge[j];
            uint2 p1 = g_edge[j + 1];
            uint2 p2 = g_edge[j + 2];
            uint2 p3 = g_edge[j + 3];
            float2 f0 = __half22float2(hp[(long long)p0.x * 32 + lane]);
            float2 f1 = __half22float2(hp[(long long)p1.x * 32 + lane]);
            float2 f2 = __half22float2(hp[(long long)p2.x * 32 + lane]);
            float2 f3 = __half22float2(hp[(long long)p3.x * 32 + lane]);
            float n0 = __uint_as_float(p0.y);
            float n1 = __uint_as_float(p1.y);
            float n2 = __uint_as_float(p2.y);
            float n3 = __uint_as_float(p3.y);
            a0 = fmaf(n0, f0.x, a0); a1 = fmaf(n0, f0.y, a1);
            a0 = fmaf(n1, f1.x, a0); a1 = fmaf(n1, f1.y, a1);
            a0 = fmaf(n2, f2.x, a0); a1 = fmaf(n2, f2.y, a1);
            a0 = fmaf(n3, f3.x, a0); a1 = fmaf(n3, f3.y, a1);
        }
        for (; j < end; j++) {
            uint2 p0 = g_edge[j];
            float2 f0 = __half22float2(hp[(long long)p0.x * 32 + lane]);
            float nn = __uint_as_float(p0.y);
            a0 = fmaf(nn, f0.x, a0);
            a1 = fmaf(nn, f0.y, a1);
        }

        float v0 = fmaxf(a0 + b0, 0.f);
        float v1 = fmaxf(a1 + b1, 0.f);
        if (xo) {
            // coalesced float2 store: features (2l, 2l+1)
            ((float2*)(xo + (long long)i * D))[lane] = make_float2(v0, v1);
        }

        float dot = v0 * wg0 + v1 * wg1;
#pragma unroll
        for (int off = 16; off > 0; off >>= 1)
            dot += __shfl_xor_sync(0xffffffffu, dot, off);
        float sg = 1.0f / (1.0f + expf(-(dot + bgv)));  // sigmoid gate
        float w = expf(sg);                             // softmax numerator
        s0 += w * v0;
        s1 += w * v1;
        if (lane == 0) z += w;
    }

    // block-level reduction of pool partials, one atomic set per block
    ps0[wlocal][lane] = s0;
    ps1[wlocal][lane] = s1;
    if (lane == 0) pz[wlocal] = z;
    __syncthreads();
    if (wlocal == 0) {
        float t0 = 0.f, t1 = 0.f, tz = 0.f;
#pragma unroll
        for (int w8 = 0; w8 < 8; w8++) {
            t0 += ps0[w8][lane];
            t1 += ps1[w8][lane];
            if (lane == 0) tz += pz[w8];
        }
        atomicAdd(&g_S[layer * D + 2 * lane], t0);
        atomicAdd(&g_S[layer * D + 2 * lane + 1], t1);
        if (lane == 0) atomicAdd(&g_Z[layer], tz);
    }
}

// ---------------- final divide ----------------------------------------------------
__global__ void k_out(float* __restrict__ out) {
    int t = threadIdx.x;
    if (t < 3 * D) out[t] = g_S[t] / g_Z[t / D];
}

// ---------------- launch ----------------------------------------------------------
extern "C" void kernel_launch(void* const* d_in, const int* in_sizes, int n_in,
                              void* d_out, int out_size) {
    const float* x     = (const float*)d_in[0];
    const void*  ei    = d_in[1];
    const float* ea    = (const float*)d_in[2];
    const float* aaaaa = (const float*)d_in[3];
    const float* W[3]  = {(const float*)d_in[4], (const float*)d_in[6], (const float*)d_in[8]};
    const float* b[3]  = {(const float*)d_in[5], (const float*)d_in[7], (const float*)d_in[9]};
    const float* wg[3] = {(const float*)d_in[10], (const float*)d_in[12], (const float*)d_in[14]};
    const float* bg[3] = {(const float*)d_in[11], (const float*)d_in[13], (const float*)d_in[15]};
    float* out = (float*)d_out;

    int N = in_sizes[0] / D;     // 100000
    int E = in_sizes[2] / EF;    // 1250000
    int nblk = (N + SCAN_B - 1) / SCAN_B;

    k_init<<<1, 256>>>(aaaaa, (const int*)ei);
    k_deginit<<<(N + 255) / 256, 256>>>(N);
    k_decode<<<(E + 255) / 256, 256>>>(ei, E);
    k_ewdeg<<<(E + 255) / 256, 256>>>(ea, E);
    k_dinv<<<(N + 255) / 256, 256>>>(N);
    k_scanA<<<nblk, SCAN_B>>>(N);
    k_scanB<<<1, 32>>>(nblk);
    k_scanC<<<nblk, SCAN_B>>>(N);
    k_build<<<(E + 255) / 256, 256>>>(E);

    // layer 1: x(ext) -> h -> bufA, pool 0
    k_gemm<<<(N + 127) / 128, 128>>>(x, 0, W[0], N);
    k_aggpool<<<1024, 256>>>(1, b[0], wg[0], bg[0], 0, N);
    // layer 2: bufA -> h -> bufB, pool 1
    k_gemm<<<(N + 127) / 128, 128>>>(x, 1, W[1], N);
    k_aggpool<<<1024, 256>>>(2, b[1], wg[1], bg[1], 1, N);
    // layer 3: bufB -> h -> (pool only), pool 2
    k_gemm<<<(N + 127) / 128, 128>>>(x, 2, W[2], N);
    k_aggpool<<<1024, 256>>>(0, b[2], wg[2], bg[2], 2, N);

    k_out<<<1, 192>>>(out);
}

// round 8
// speedup vs baseline: 1.2806x; 1.1183x over previous
#include <cuda_runtime.h>
#include <cuda_fp16.h>

#define NN 100000
#define NE 1250000
#define D  64
#define EF 13
#define SCAN_B 1024

// ---------------- scratch (device globals; no allocation allowed) ----------------
__device__ float g_sm[EF];
__device__ int   g_is64;
__device__ int   g_rows[NE];
__device__ int   g_cols[NE];
__device__ float g_ew[NE];
__device__ float g_deg[NN];
__device__ float g_dinv[NN];
__device__ float g_dsq[NN];
__device__ int   g_cnt[NN];       // in-degree (edge count per dest)
__device__ int   g_start[NN];     // CSR offsets
__device__ int   g_cursor[NN];    // build cursors
__device__ int   g_bsum[128];     // scan partials
__device__ int   g_boff[128];
__device__ __align__(16) uint2 g_edge[NE];       // packed (row, norm) sorted by col
__device__ __align__(16) __half g_hh[NN * D];    // GEMM output, fp16 (gather payload)
__device__ __align__(16) float g_bufA[NN * D];   // x1
__device__ __align__(16) float g_bufB[NN * D];   // x2
__device__ float g_S[3 * D];      // pool numerators
__device__ float g_Z[3];          // pool denominators

// ---------------- init: softmax(aaaaa), zero pool accs, detect index dtype -------
__global__ void k_init(const float* __restrict__ aaaaa,
                       const int* __restrict__ ei_raw) {
    int t = threadIdx.x;
    if (t < 3 * D) g_S[t] = 0.0f;
    if (t < 3)     g_Z[t] = 0.0f;
    if (t == 0) {
        float v[EF];
        float m = -1e30f;
        for (int j = 0; j < EF; j++) { v[j] = aaaaa[j]; m = fmaxf(m, v[j]); }
        float s = 0.0f;
        for (int j = 0; j < EF; j++) { v[j] = expf(v[j] - m); s += v[j]; }
        for (int j = 0; j < EF; j++) g_sm[j] = v[j] / s;

        // dtype sniff: int64 indices have zero high words
        int is64 = 1;
        for (int i = 0; i < 64; i++)
            if (ei_raw[2 * i + 1] != 0) { is64 = 0; break; }
        g_is64 = is64;
    }
}

// ---------------- per-node init: deg=1 (self loop), cnt=0 ------------------------
__global__ void k_deginit(int n) {
    int i = blockIdx.x * blockDim.x + threadIdx.x;
    if (i < n) { g_deg[i] = 1.0f; g_cnt[i] = 0; }
}

// ---- decode edge_index + edge weight + per-dest count/deg (single edge pass) ----
__global__ void k_decode_ew(const void* __restrict__ ei,
                            const float* __restrict__ ea, int E) {
    int e = blockIdx.x * blockDim.x + threadIdx.x;
    if (e >= E) return;
    int r, c;
    if (g_is64) {
        const long long* p = (const long long*)ei;
        r = (int)p[e];
        c = (int)p[E + e];
    } else {
        const int* p = (const int*)ei;
        r = p[e];
        c = p[E + e];
    }
    g_rows[e] = r;
    g_cols[e] = c;

    const float* row = ea + (long long)e * EF;
    float s = 0.0f;
#pragma unroll
    for (int j = 0; j < EF; j++) s += __ldg(row + j) * g_sm[j];
    g_ew[e] = s;
    atomicAdd(&g_deg[c], s);
    atomicAdd(&g_cnt[c], 1);
}

// ---------------- deg^{-1/2} and self-loop norm -----------------------------------
__global__ void k_dinv(int n) {
    int i = blockIdx.x * blockDim.x + threadIdx.x;
    if (i >= n) return;
    float di = rsqrtf(g_deg[i]);   // deg >= 1 always
    g_dinv[i] = di;
    g_dsq[i] = di * di;
}

// ---------------- scan stage A: per-block sums of g_cnt ---------------------------
__global__ void k_scanA(int n) {
    __shared__ int sm[SCAN_B];
    int i = blockIdx.x * SCAN_B + threadIdx.x;
    sm[threadIdx.x] = (i < n) ? g_cnt[i] : 0;
    __syncthreads();
    for (int off = SCAN_B / 2; off > 0; off >>= 1) {
        if (threadIdx.x < off) sm[threadIdx.x] += sm[threadIdx.x + off];
        __syncthreads();
    }
    if (threadIdx.x == 0) g_bsum[blockIdx.x] = sm[0];
}

// ---------------- scan stage B: exclusive scan of block sums ----------------------
__global__ void k_scanB(int nblk) {
    if (threadIdx.x == 0) {
        int run = 0;
        for (int i = 0; i < nblk; i++) { g_boff[i] = run; run += g_bsum[i]; }
    }
}

// ---------------- scan stage C: in-block exclusive scan + base; init cursor -------
__global__ void k_scanC(int n) {
    __shared__ int sm[SCAN_B];
    int i = blockIdx.x * SCAN_B + threadIdx.x;
    int v = (i < n) ? g_cnt[i] : 0;
    sm[threadIdx.x] = v;
    __syncthreads();
    for (int off = 1; off < SCAN_B; off <<= 1) {
        int t = (threadIdx.x >= off) ? sm[threadIdx.x - off] : 0;
        __syncthreads();
        sm[threadIdx.x] += t;
        __syncthreads();
    }
    if (i < n) {
        int st = g_boff[blockIdx.x] + sm[threadIdx.x] - v;  // exclusive
        g_start[i] = st;
        g_cursor[i] = st;
    }
}

// ---------------- CSR build: pack (row, norm) sorted by destination ---------------
__global__ void k_build(int E) {
    int e = blockIdx.x * blockDim.x + threadIdx.x;
    if (e >= E) return;
    int r = g_rows[e];
    int c = g_cols[e];
    float nrm = g_dinv[r] * g_ew[e] * g_dinv[c];
    int pos = atomicAdd(&g_cursor[c], 1);
    g_edge[pos] = make_uint2((unsigned)r, __float_as_uint(nrm));
}

// ---------------- GEMM: h = x @ W  (thread per row, W in smem; fp16 output) -------
__global__ void k_gemm(const float* __restrict__ xext, int sel,
                       const float* __restrict__ W, int n) {
    __shared__ float Ws[D * D];
    for (int i = threadIdx.x; i < D * D; i += blockDim.x) Ws[i] = W[i];
    __syncthreads();

    const float* x = (sel == 0) ? xext : ((sel == 1) ? g_bufA : g_bufB);
    int row = blockIdx.x * blockDim.x + threadIdx.x;
    if (row >= n) return;

    const float4* xr = (const float4*)(x + (long long)row * D);
    float4 acc[16];
#pragma unroll
    for (int c = 0; c < 16; c++) acc[c] = make_float4(0.f, 0.f, 0.f, 0.f);

#pragma unroll
    for (int k4 = 0; k4 < 16; k4++) {
        float4 xv = xr[k4];
        float xa[4] = {xv.x, xv.y, xv.z, xv.w};
#pragma unroll
        for (int kk = 0; kk < 4; kk++) {
            float xk = xa[kk];
            const float4* wrow = (const float4*)&Ws[(k4 * 4 + kk) * D];
#pragma unroll
            for (int c = 0; c < 16; c++) {
                float4 wv = wrow[c];
                acc[c].x += xk * wv.x;
                acc[c].y += xk * wv.y;
                acc[c].z += xk * wv.z;
                acc[c].w += xk * wv.w;
            }
        }
    }
    __half2* ho = (__half2*)(g_hh + (long long)row * D);
#pragma unroll
    for (int c = 0; c < 16; c++) {
        ho[2 * c]     = __float22half2_rn(make_float2(acc[c].x, acc[c].y));
        ho[2 * c + 1] = __float22half2_rn(make_float2(acc[c].z, acc[c].w));
    }
}

// ------ fused CSR aggregate (+self loop, fp16 payload) + bias/relu + pool ---------
// warp per node (grid-stride); lane owns features (2l, 2l+1).
// Records loaded lane-parallel (1 coalesced load per <=32 edges), broadcast via
// shfl -> payload loads depend only on registers -> MLP ~= node degree.
__global__ void __launch_bounds__(256) k_aggpool(
        int sel_out, const float* __restrict__ b,
        const float* __restrict__ wg, const float* __restrict__ bg,
        int layer, int n) {
    __shared__ float ps0[8][32];
    __shared__ float ps1[8][32];
    __shared__ float pz[8];
    float* xo = (sel_out == 1) ? g_bufA : ((sel_out == 2) ? g_bufB : 0);
    int lane = threadIdx.x & 31;
    int wlocal = threadIdx.x >> 5;
    int warp = (blockIdx.x * blockDim.x + threadIdx.x) >> 5;
    int nwarps = (gridDim.x * blockDim.x) >> 5;

    float wg0 = wg[2 * lane], wg1 = wg[2 * lane + 1];
    float b0 = b[2 * lane],  b1 = b[2 * lane + 1];
    float bgv = bg[0];

    const __half2* hp = (const __half2*)g_hh;   // element index = row*32 + lane

    float s0 = 0.f, s1 = 0.f, z = 0.f;

    for (int i = warp; i < n; i += nwarps) {
        float ds = g_dsq[i];
        float2 hv = __half22float2(hp[(long long)i * 32 + lane]);
        float a0 = ds * hv.x;
        float a1 = ds * hv.y;

        int j0 = g_start[i];
        int cnt = g_cnt[i];

        for (int base = 0; base < cnt; base += 32) {
            int m = min(32, cnt - base);
            // lane-parallel record fetch: one coalesced transaction for <=32 edges
            uint2 rec = make_uint2(0u, 0u);
            if (lane < m) rec = g_edge[j0 + base + lane];

            int t = 0;
            for (; t + 1 < m; t += 2) {
                unsigned rx0 = __shfl_sync(0xffffffffu, rec.x, t);
                unsigned ry0 = __shfl_sync(0xffffffffu, rec.y, t);
                unsigned rx1 = __shfl_sync(0xffffffffu, rec.x, t + 1);
                unsigned ry1 = __shfl_sync(0xffffffffu, rec.y, t + 1);
                float2 f0 = __half22float2(hp[(long long)rx0 * 32 + lane]);
                float2 f1 = __half22float2(hp[(long long)rx1 * 32 + lane]);
                float n0 = __uint_as_float(ry0);
                float n1 = __uint_as_float(ry1);
                a0 = fmaf(n0, f0.x, a0); a1 = fmaf(n0, f0.y, a1);
                a0 = fmaf(n1, f1.x, a0); a1 = fmaf(n1, f1.y, a1);
            }
            if (t < m) {
                unsigned rx0 = __shfl_sync(0xffffffffu, rec.x, t);
                unsigned ry0 = __shfl_sync(0xffffffffu, rec.y, t);
                float2 f0 = __half22float2(hp[(long long)rx0 * 32 + lane]);
                float n0 = __uint_as_float(ry0);
                a0 = fmaf(n0, f0.x, a0); a1 = fmaf(n0, f0.y, a1);
            }
        }

        float v0 = fmaxf(a0 + b0, 0.f);
        float v1 = fmaxf(a1 + b1, 0.f);
        if (xo) {
            // coalesced float2 store: features (2l, 2l+1)
            ((float2*)(xo + (long long)i * D))[lane] = make_float2(v0, v1);
        }

        float dot = v0 * wg0 + v1 * wg1;
#pragma unroll
        for (int off = 16; off > 0; off >>= 1)
            dot += __shfl_xor_sync(0xffffffffu, dot, off);
        float sg = 1.0f / (1.0f + expf(-(dot + bgv)));  // sigmoid gate
        float w = expf(sg);                             // softmax numerator
        s0 += w * v0;
        s1 += w * v1;
        if (lane == 0) z += w;
    }

    // block-level reduction of pool partials, one atomic set per block
    ps0[wlocal][lane] = s0;
    ps1[wlocal][lane] = s1;
    if (lane == 0) pz[wlocal] = z;
    __syncthreads();
    if (wlocal == 0) {
        float t0 = 0.f, t1 = 0.f, tz = 0.f;
#pragma unroll
        for (int w8 = 0; w8 < 8; w8++) {
            t0 += ps0[w8][lane];
            t1 += ps1[w8][lane];
            if (lane == 0) tz += pz[w8];
        }
        atomicAdd(&g_S[layer * D + 2 * lane], t0);
        atomicAdd(&g_S[layer * D + 2 * lane + 1], t1);
        if (lane == 0) atomicAdd(&g_Z[layer], tz);
    }
}

// ---------------- final divide ----------------------------------------------------
__global__ void k_out(float* __restrict__ out) {
    int t = threadIdx.x;
    if (t < 3 * D) out[t] = g_S[t] / g_Z[t / D];
}

// ---------------- launch ----------------------------------------------------------
extern "C" void kernel_launch(void* const* d_in, const int* in_sizes, int n_in,
                              void* d_out, int out_size) {
    const float* x     = (const float*)d_in[0];
    const void*  ei    = d_in[1];
    const float* ea    = (const float*)d_in[2];
    const float* aaaaa = (const float*)d_in[3];
    const float* W[3]  = {(const float*)d_in[4], (const float*)d_in[6], (const float*)d_in[8]};
    const float* b[3]  = {(const float*)d_in[5], (const float*)d_in[7], (const float*)d_in[9]};
    const float* wg[3] = {(const float*)d_in[10], (const float*)d_in[12], (const float*)d_in[14]};
    const float* bg[3] = {(const float*)d_in[11], (const float*)d_in[13], (const float*)d_in[15]};
    float* out = (float*)d_out;

    int N = in_sizes[0] / D;     // 100000
    int E = in_sizes[2] / EF;    // 1250000
    int nblk = (N + SCAN_B - 1) / SCAN_B;

    k_init<<<1, 256>>>(aaaaa, (const int*)ei);
    k_deginit<<<(N + 255) / 256, 256>>>(N);
    k_decode_ew<<<(E + 255) / 256, 256>>>(ei, ea, E);
    k_dinv<<<(N + 255) / 256, 256>>>(N);
    k_scanA<<<nblk, SCAN_B>>>(N);
    k_scanB<<<1, 32>>>(nblk);
    k_scanC<<<nblk, SCAN_B>>>(N);
    k_build<<<(E + 255) / 256, 256>>>(E);

    // layer 1: x(ext) -> h -> bufA, pool 0
    k_gemm<<<(N + 127) / 128, 128>>>(x, 0, W[0], N);
    k_aggpool<<<1024, 256>>>(1, b[0], wg[0], bg[0], 0, N);
    // layer 2: bufA -> h -> bufB, pool 1
    k_gemm<<<(N + 127) / 128, 128>>>(x, 1, W[1], N);
    k_aggpool<<<1024, 256>>>(2, b[1], wg[1], bg[1], 1, N);
    // layer 3: bufB -> h -> (pool only), pool 2
    k_gemm<<<(N + 127) / 128, 128>>>(x, 2, W[2], N);
    k_aggpool<<<1024, 256>>>(0, b[2], wg[2], bg[2], 2, N);

    k_out<<<1, 192>>>(out);
}